// round 3
// baseline (speedup 1.0000x reference)
#include <cuda_runtime.h>
#include <cuda_fp16.h>
#include <cstdint>

// ---------------------------------------------------------------------------
// Problem: B=32, T=4096, K=1024 (2H), N=512 (DFF)
// GEMM uh = h[131072,1024] x U^T[1024,512] via mma.sync m16n8k16 (HMMA),
// fused tanh/V epilogue -> energy, fused energy.h context from smem fp16 h.
// CTA: 64 t-rows, full K resident in smem fp16, 4 N-passes of 128.
// ---------------------------------------------------------------------------
#define BATCH   32
#define TSEQ    4096
#define KDIM    1024
#define NDFF    512
#define MTILE   64
#define KCH     64                 // K chunk
#define NCHUNKS 16                 // KDIM / KCH
#define NPASSES 4                  // NDFF / 128
#define NTILES  (TSEQ / MTILE)     // 64
#define NCTAS   (BATCH * NTILES)   // 2048

// Device scratch
__device__ __align__(128) __half g_Uh[NDFF * KDIM];                 // 1 MB fp16 U [f][e]
__device__ __align__(128) float  g_ws[BATCH * NDFF];                // ws + Wb + Ub
__device__ __align__(128) float  g_partial[NCTAS * KDIM];           // 8 MB tile contexts

// Shared layout (bytes)
#define SM_WS   0                      // 512 f
#define SM_V    2048                   // 512 f
#define SM_EN   4096                   // 8*64 f
#define SM_ENF  6144                   // 64 f
#define SM_A    8192                   // 16 slices x (64 x 128B) = 131072
#define SM_B    139264                 // 4 bufs x 16384 = 65536
#define SMEM_TOTAL 204800

#define SWZ(off) ((uint32_t)(off) ^ ((((uint32_t)(off)) >> 3) & 0x70u))

__device__ __forceinline__ uint32_t smem_u32(const void* p) {
    uint32_t a;
    asm("{ .reg .u64 t; cvta.to.shared.u64 t, %1; cvt.u32.u64 %0, t; }"
        : "=r"(a) : "l"(p));
    return a;
}

__device__ __forceinline__ void cp_async16(uint32_t dst, const void* src) {
    asm volatile("cp.async.cg.shared.global [%0], [%1], 16;"
                 :: "r"(dst), "l"(src) : "memory");
}
#define CP_COMMIT() asm volatile("cp.async.commit_group;" ::: "memory")
#define CP_WAIT3()  asm volatile("cp.async.wait_group 3;" ::: "memory")

__device__ __forceinline__ void ldsm4(uint32_t& r0, uint32_t& r1, uint32_t& r2,
                                      uint32_t& r3, uint32_t addr) {
    asm volatile("ldmatrix.sync.aligned.m8n8.x4.shared.b16 {%0,%1,%2,%3}, [%4];"
                 : "=r"(r0), "=r"(r1), "=r"(r2), "=r"(r3) : "r"(addr));
}

__device__ __forceinline__ void mma16816(float* c, uint32_t a0, uint32_t a1,
                                         uint32_t a2, uint32_t a3,
                                         uint32_t b0, uint32_t b1) {
    asm volatile(
        "mma.sync.aligned.m16n8k16.row.col.f32.f16.f16.f32 "
        "{%0,%1,%2,%3}, {%4,%5,%6,%7}, {%8,%9}, {%0,%1,%2,%3};"
        : "+f"(c[0]), "+f"(c[1]), "+f"(c[2]), "+f"(c[3])
        : "r"(a0), "r"(a1), "r"(a2), "r"(a3), "r"(b0), "r"(b1));
}

// ---------------------------------------------------------------------------
// Prep kernels
// ---------------------------------------------------------------------------
__global__ void k_convU(const float4* __restrict__ U4) {
    int i = blockIdx.x * blockDim.x + threadIdx.x;     // 0..131071 (x4 elems)
    float4 v = U4[i];
    __half2 p0 = __floats2half2_rn(v.x, v.y);
    __half2 p1 = __floats2half2_rn(v.z, v.w);
    uint2 u;
    u.x = *reinterpret_cast<uint32_t*>(&p0);
    u.y = *reinterpret_cast<uint32_t*>(&p1);
    *reinterpret_cast<uint2*>(&g_Uh[i * 4]) = u;
}

__global__ void k_ws(const float* __restrict__ s, const float* __restrict__ W,
                     const float* __restrict__ Wb, const float* __restrict__ Ub) {
    __shared__ float ssh[512];
    int b = blockIdx.x;
    int f = threadIdx.x;
    ssh[f] = s[b * 512 + f];
    __syncthreads();
    float acc = Wb[f] + Ub[f];
    const float4* Wr = reinterpret_cast<const float4*>(W + (size_t)f * 512);
#pragma unroll 4
    for (int e4 = 0; e4 < 128; e4++) {
        float4 w = Wr[e4];
        acc = fmaf(ssh[e4 * 4 + 0], w.x, acc);
        acc = fmaf(ssh[e4 * 4 + 1], w.y, acc);
        acc = fmaf(ssh[e4 * 4 + 2], w.z, acc);
        acc = fmaf(ssh[e4 * 4 + 3], w.w, acc);
    }
    g_ws[b * 512 + f] = acc;
}

__global__ void k_reduce(float* __restrict__ out) {
    int o = blockIdx.x * blockDim.x + threadIdx.x;     // 0..32767
    int b = o >> 10;
    int e = o & 1023;
    float acc = 0.f;
#pragma unroll
    for (int tt = 0; tt < NTILES; tt++)
        acc += g_partial[((size_t)(b * NTILES + tt) << 10) + e];
    out[o] = acc;
}

// ---------------------------------------------------------------------------
// Main kernel
// ---------------------------------------------------------------------------
__global__ __launch_bounds__(256, 1)
void k_main(const float* __restrict__ h, const float* __restrict__ V,
            const float* __restrict__ Vb) {
    extern __shared__ char smem[];
    const uint32_t sb = smem_u32(smem);
    const int tid  = threadIdx.x;
    const int wid  = tid >> 5;
    const int lane = tid & 31;
    const int b    = blockIdx.x >> 6;

    float* ws_s  = reinterpret_cast<float*>(smem + SM_WS);
    float* V_s   = reinterpret_cast<float*>(smem + SM_V);
    float* en_s  = reinterpret_cast<float*>(smem + SM_EN);
    float* enf_s = reinterpret_cast<float*>(smem + SM_ENF);

    for (int i = tid; i < NDFF; i += 256) {
        ws_s[i] = g_ws[b * NDFF + i];
        V_s[i]  = V[i];
        en_s[i] = 0.f;
    }

    const float* hB = h + (size_t)blockIdx.x * (MTILE * KDIM);

    // ---- per-thread copy / ldmatrix address precompute ----
    // A global load / smem store mapping (pass 0): 2 groups of 8 floats
    const int g0 = tid, g1 = tid + 256;
    const int m0 = g0 >> 3, ks0 = g0 & 7;
    const int m1 = g1 >> 3, ks1 = g1 & 7;
    const uint32_t sa0 = SWZ(m0 * 128 + ks0 * 16);
    const uint32_t sa1 = SWZ(m1 * 128 + ks1 * 16);

    // B cp.async mapping: 4 x 16B per thread per chunk
    uint32_t bdst[4];
    int      bn[4], bseg[4];
#pragma unroll
    for (int it = 0; it < 4; it++) {
        int idx  = it * 256 + tid;
        bn[it]   = idx >> 3;
        bseg[it] = idx & 7;
        bdst[it] = SWZ(bn[it] * 128 + bseg[it] * 16);
    }

    // ldmatrix offsets
    const int r    = lane & 7;
    const int selA = (lane >> 3) & 1;        // m +8 select
    const int selK = (lane >> 4) & 1;        // k +8 select (A)
    uint32_t aoff[4][4];
#pragma unroll
    for (int mi = 0; mi < 4; mi++)
#pragma unroll
        for (int ki = 0; ki < 4; ki++)
            aoff[mi][ki] = SWZ((mi * 16 + selA * 8 + r) * 128 +
                               (ki * 16 + selK * 8) * 2);
    const int selKb = (lane >> 3) & 1;       // k +8 select (B)
    const int selNb = (lane >> 4) & 1;       // n +8 select (B)
    uint32_t boff[4];
#pragma unroll
    for (int ki = 0; ki < 4; ki++)
        boff[ki] = SWZ((wid * 16 + selNb * 8 + r) * 128 +
                       (ki * 16 + selKb * 8) * 2);

    float ra[16];   // A fp32 staging (pass 0)

    // =======================================================================
    for (int np = 0; np < NPASSES; np++) {
        const __half* Ubase = g_Uh + (size_t)(np * 128) * KDIM;

        float acc[4][2][4];
#pragma unroll
        for (int mi = 0; mi < 4; mi++)
#pragma unroll
            for (int ni = 0; ni < 2; ni++)
#pragma unroll
                for (int j = 0; j < 4; j++) acc[mi][ni][j] = 0.f;

        // prologue: 3 B chunks in flight
#pragma unroll
        for (int cc = 0; cc < 3; cc++) {
            const __half* src = Ubase + cc * KCH;
            uint32_t dst = sb + SM_B + cc * 16384;
#pragma unroll
            for (int it = 0; it < 4; it++)
                cp_async16(dst + bdst[it], src + bn[it] * KDIM + bseg[it] * 8);
            CP_COMMIT();
        }
        if (np == 0) {
            // A chunk 0: LDG -> cvt -> STS; LDG chunk 1
            {
                const float* p0 = hB + m0 * KDIM + ks0 * 8;
                const float* p1 = hB + m1 * KDIM + ks1 * 8;
#pragma unroll
                for (int j = 0; j < 8; j++) ra[j] = p0[j];
#pragma unroll
                for (int j = 0; j < 8; j++) ra[8 + j] = p1[j];
                uint4 u0, u1;
                __half2 t;
                t = __floats2half2_rn(ra[0], ra[1]);  u0.x = *(uint32_t*)&t;
                t = __floats2half2_rn(ra[2], ra[3]);  u0.y = *(uint32_t*)&t;
                t = __floats2half2_rn(ra[4], ra[5]);  u0.z = *(uint32_t*)&t;
                t = __floats2half2_rn(ra[6], ra[7]);  u0.w = *(uint32_t*)&t;
                t = __floats2half2_rn(ra[8], ra[9]);  u1.x = *(uint32_t*)&t;
                t = __floats2half2_rn(ra[10], ra[11]); u1.y = *(uint32_t*)&t;
                t = __floats2half2_rn(ra[12], ra[13]); u1.z = *(uint32_t*)&t;
                t = __floats2half2_rn(ra[14], ra[15]); u1.w = *(uint32_t*)&t;
                *reinterpret_cast<uint4*>(smem + SM_A + sa0) = u0;
                *reinterpret_cast<uint4*>(smem + SM_A + sa1) = u1;
            }
            {
                const float* p0 = hB + m0 * KDIM + 64 + ks0 * 8;
                const float* p1 = hB + m1 * KDIM + 64 + ks1 * 8;
#pragma unroll
                for (int j = 0; j < 8; j++) ra[j] = p0[j];
#pragma unroll
                for (int j = 0; j < 8; j++) ra[8 + j] = p1[j];
            }
        }

        // ---------------- K mainloop ----------------
#pragma unroll 1
        for (int c = 0; c < NCHUNKS; c++) {
            __syncthreads();    // all warps done with mma c-1 (buffer reuse safe)
            if (c + 3 < NCHUNKS) {
                const __half* src = Ubase + (c + 3) * KCH;
                uint32_t dst = sb + SM_B + ((c + 3) & 3) * 16384;
#pragma unroll
                for (int it = 0; it < 4; it++)
                    cp_async16(dst + bdst[it], src + bn[it] * KDIM + bseg[it] * 8);
            }
            CP_COMMIT();
            if (np == 0) {
                if (c + 1 < NCHUNKS) {
                    // cvt+STS A_{c+1} (regs), then LDG A_{c+2}
                    uint4 u0, u1;
                    __half2 t;
                    t = __floats2half2_rn(ra[0], ra[1]);  u0.x = *(uint32_t*)&t;
                    t = __floats2half2_rn(ra[2], ra[3]);  u0.y = *(uint32_t*)&t;
                    t = __floats2half2_rn(ra[4], ra[5]);  u0.z = *(uint32_t*)&t;
                    t = __floats2half2_rn(ra[6], ra[7]);  u0.w = *(uint32_t*)&t;
                    t = __floats2half2_rn(ra[8], ra[9]);  u1.x = *(uint32_t*)&t;
                    t = __floats2half2_rn(ra[10], ra[11]); u1.y = *(uint32_t*)&t;
                    t = __floats2half2_rn(ra[12], ra[13]); u1.z = *(uint32_t*)&t;
                    t = __floats2half2_rn(ra[14], ra[15]); u1.w = *(uint32_t*)&t;
                    char* slice = smem + SM_A + (c + 1) * 8192;
                    *reinterpret_cast<uint4*>(slice + sa0) = u0;
                    *reinterpret_cast<uint4*>(slice + sa1) = u1;
                    if (c + 2 < NCHUNKS) {
                        const float* p0 = hB + m0 * KDIM + (c + 2) * KCH + ks0 * 8;
                        const float* p1 = hB + m1 * KDIM + (c + 2) * KCH + ks1 * 8;
#pragma unroll
                        for (int j = 0; j < 8; j++) ra[j] = p0[j];
#pragma unroll
                        for (int j = 0; j < 8; j++) ra[8 + j] = p1[j];
                    }
                }
            }
            CP_WAIT3();
            __syncthreads();    // B_c visible to all

            const uint32_t abase = sb + SM_A + ((uint32_t)c << 13);
            const uint32_t bbase = sb + SM_B + ((uint32_t)(c & 3) << 14);
#pragma unroll
            for (int ki = 0; ki < 4; ki++) {
                uint32_t b0, b1, b2, b3;
                ldsm4(b0, b1, b2, b3, bbase + boff[ki]);
#pragma unroll
                for (int mi = 0; mi < 4; mi++) {
                    uint32_t a0, a1, a2, a3;
                    ldsm4(a0, a1, a2, a3, abase + aoff[mi][ki]);
                    mma16816(acc[mi][0], a0, a1, a2, a3, b0, b1);
                    mma16816(acc[mi][1], a0, a1, a2, a3, b2, b3);
                }
            }
        }

        // ---------------- epilogue: energy partials ----------------
#pragma unroll
        for (int mi = 0; mi < 4; mi++) {
#pragma unroll
            for (int h2 = 0; h2 < 2; h2++) {
                float s = 0.f;
#pragma unroll
                for (int ni = 0; ni < 2; ni++) {
#pragma unroll
                    for (int j = 0; j < 2; j++) {
                        float val = acc[mi][ni][h2 * 2 + j];
                        int f = np * 128 + wid * 16 + ni * 8 + ((lane & 3) << 1) + j;
                        float z = ws_s[f] + val;
                        z = fminf(fmaxf(z, -15.f), 15.f);
                        float e2 = __expf(2.f * z);
                        float x = __fdividef(e2 - 1.f, e2 + 1.f);
                        s = fmaf(V_s[f], x, s);
                    }
                }
                s += __shfl_xor_sync(0xffffffffu, s, 1);
                s += __shfl_xor_sync(0xffffffffu, s, 2);
                if ((lane & 3) == 0)
                    en_s[(wid << 6) + mi * 16 + h2 * 8 + (lane >> 2)] += s;
            }
        }
    }

    // ---------------- finalize energy ----------------
    __syncthreads();
    if (tid < MTILE) {
        float e = Vb[0];
#pragma unroll
        for (int w = 0; w < 8; w++) e += en_s[(w << 6) + tid];
        enf_s[tid] = e;
    }
    __syncthreads();

    // ---------------- context partial from smem fp16 h ----------------
    {
        const int e0 = tid << 2;           // 4 elements per thread
        const int ch = e0 >> 6;
        const int wi = e0 & 63;
        char* slice = smem + SM_A + (ch << 13);
        float a0 = 0.f, a1 = 0.f, a2 = 0.f, a3 = 0.f;
#pragma unroll 8
        for (int m = 0; m < MTILE; m++) {
            uint32_t off = SWZ(m * 128 + wi * 2);
            uint2 v = *reinterpret_cast<uint2*>(slice + off);
            __half2 h01 = *reinterpret_cast<__half2*>(&v.x);
            __half2 h23 = *reinterpret_cast<__half2*>(&v.y);
            float2 f01 = __half22float2(h01);
            float2 f23 = __half22float2(h23);
            float en = enf_s[m];
            a0 = fmaf(en, f01.x, a0);
            a1 = fmaf(en, f01.y, a1);
            a2 = fmaf(en, f23.x, a2);
            a3 = fmaf(en, f23.y, a3);
        }
        float4 o = make_float4(a0, a1, a2, a3);
        *reinterpret_cast<float4*>(g_partial + ((size_t)blockIdx.x << 10) + e0) = o;
    }
}

// ---------------------------------------------------------------------------
// Launch
// ---------------------------------------------------------------------------
extern "C" void kernel_launch(void* const* d_in, const int* in_sizes, int n_in,
                              void* d_out, int out_size) {
    (void)in_sizes; (void)n_in; (void)out_size;
    const float* s  = (const float*)d_in[0];   // [32, 512]
    const float* h  = (const float*)d_in[1];   // [32, 4096, 1024]
    const float* Ww = (const float*)d_in[2];   // [512, 512]
    const float* Wb = (const float*)d_in[3];   // [512]
    const float* Uw = (const float*)d_in[4];   // [512, 1024]
    const float* Ub = (const float*)d_in[5];   // [512]
    const float* Vw = (const float*)d_in[6];   // [1, 512]
    const float* Vb = (const float*)d_in[7];   // [1]
    float* out = (float*)d_out;                // [32, 1024]

    cudaFuncSetAttribute(k_main, cudaFuncAttributeMaxDynamicSharedMemorySize,
                         SMEM_TOTAL);

    k_convU<<<512, 256>>>((const float4*)Uw);
    k_ws<<<BATCH, 512>>>(s, Ww, Wb, Ub);
    k_main<<<NCTAS, 256, SMEM_TOTAL>>>(h, Vw, Vb);
    k_reduce<<<128, 256>>>(out);
}

// round 4
// speedup vs baseline: 1.2534x; 1.2534x over previous
#include <cuda_runtime.h>
#include <cuda_fp16.h>
#include <cstdint>

// ---------------------------------------------------------------------------
// B=32, T=4096, K=1024 (2H), N=512 (DFF)
// Single N-pass HMMA GEMM: warp tile M32 x N128, K-chunk 32, 3-stage cp.async.
// ---------------------------------------------------------------------------
#define BATCH   32
#define TSEQ    4096
#define KDIM    1024
#define NDFF    512
#define MTILE   64
#define KCH     32
#define NCHUNKS 32                 // KDIM / KCH
#define NTILES  (TSEQ / MTILE)     // 64
#define NCTAS   (BATCH * NTILES)   // 2048

__device__ __align__(128) __half g_Uh[NDFF * KDIM];             // 1 MB fp16 U [f][e]
__device__ __align__(128) float  g_ws[BATCH * NDFF];
__device__ __align__(128) float  g_partial[NCTAS * KDIM];       // 8 MB

// Shared layout (bytes)
#define SM_WS   0                       // 512 f
#define SM_V    2048                    // 512 f
#define SM_EN   4096                    // 8*64 f
#define SM_ENF  6144                    // 64 f
#define SM_A    8192                    // 3 stages x 4096
#define SM_B    20480                   // 3 stages x 32768
#define SMEM_TOTAL 118784

#define SWZ(off) ((uint32_t)(off) ^ ((((uint32_t)(off)) >> 3) & 0x70u))

__device__ __forceinline__ uint32_t smem_u32(const void* p) {
    uint32_t a;
    asm("{ .reg .u64 t; cvta.to.shared.u64 t, %1; cvt.u32.u64 %0, t; }"
        : "=r"(a) : "l"(p));
    return a;
}
__device__ __forceinline__ void cp_async16(uint32_t dst, const void* src) {
    asm volatile("cp.async.cg.shared.global [%0], [%1], 16;"
                 :: "r"(dst), "l"(src) : "memory");
}
#define CP_COMMIT() asm volatile("cp.async.commit_group;" ::: "memory")
#define CP_WAIT1()  asm volatile("cp.async.wait_group 1;" ::: "memory")

__device__ __forceinline__ void ldsm4(uint32_t& r0, uint32_t& r1, uint32_t& r2,
                                      uint32_t& r3, uint32_t addr) {
    asm volatile("ldmatrix.sync.aligned.m8n8.x4.shared.b16 {%0,%1,%2,%3}, [%4];"
                 : "=r"(r0), "=r"(r1), "=r"(r2), "=r"(r3) : "r"(addr));
}
__device__ __forceinline__ void mma16816(float* c, uint32_t a0, uint32_t a1,
                                         uint32_t a2, uint32_t a3,
                                         uint32_t b0, uint32_t b1) {
    asm volatile(
        "mma.sync.aligned.m16n8k16.row.col.f32.f16.f16.f32 "
        "{%0,%1,%2,%3}, {%4,%5,%6,%7}, {%8,%9}, {%0,%1,%2,%3};"
        : "+f"(c[0]), "+f"(c[1]), "+f"(c[2]), "+f"(c[3])
        : "r"(a0), "r"(a1), "r"(a2), "r"(a3), "r"(b0), "r"(b1));
}

// ---------------------------------------------------------------------------
// Prep kernels
// ---------------------------------------------------------------------------
__global__ void k_convU(const float4* __restrict__ U4) {
    int i = blockIdx.x * blockDim.x + threadIdx.x;
    float4 v = U4[i];
    __half2 p0 = __floats2half2_rn(v.x, v.y);
    __half2 p1 = __floats2half2_rn(v.z, v.w);
    uint2 u;
    u.x = *reinterpret_cast<uint32_t*>(&p0);
    u.y = *reinterpret_cast<uint32_t*>(&p1);
    *reinterpret_cast<uint2*>(&g_Uh[i * 4]) = u;
}

__global__ void k_ws(const float* __restrict__ s, const float* __restrict__ W,
                     const float* __restrict__ Wb, const float* __restrict__ Ub) {
    __shared__ float ssh[512];
    int b = blockIdx.x;
    int f = threadIdx.x;
    ssh[f] = s[b * 512 + f];
    __syncthreads();
    float acc = Wb[f] + Ub[f];
    const float4* Wr = reinterpret_cast<const float4*>(W + (size_t)f * 512);
#pragma unroll 4
    for (int e4 = 0; e4 < 128; e4++) {
        float4 w = Wr[e4];
        acc = fmaf(ssh[e4 * 4 + 0], w.x, acc);
        acc = fmaf(ssh[e4 * 4 + 1], w.y, acc);
        acc = fmaf(ssh[e4 * 4 + 2], w.z, acc);
        acc = fmaf(ssh[e4 * 4 + 3], w.w, acc);
    }
    g_ws[b * 512 + f] = acc;
}

__global__ void k_reduce(float* __restrict__ out) {
    int o = blockIdx.x * blockDim.x + threadIdx.x;
    int b = o >> 10;
    int e = o & 1023;
    float acc = 0.f;
#pragma unroll
    for (int tt = 0; tt < NTILES; tt++)
        acc += g_partial[((size_t)(b * NTILES + tt) << 10) + e];
    out[o] = acc;
}

// ---------------------------------------------------------------------------
// Main kernel: 256 threads, 8 warps = 2(M) x 4(N). Warp tile M32 x N128.
// Packed smem rows: two 64B k-rows per 128B smem row, SW128-swizzled.
// chunk addr of (row, seg8) = (row>>1)*128 + (row&1)*64 + seg8*16, then SWZ.
// ---------------------------------------------------------------------------
__global__ __launch_bounds__(256, 1)
void k_main(const float* __restrict__ h, const float* __restrict__ V,
            const float* __restrict__ Vb) {
    extern __shared__ char smem[];
    const uint32_t sb = smem_u32(smem);
    const int tid  = threadIdx.x;
    const int wid  = tid >> 5;
    const int lane = tid & 31;
    const int mg   = wid >> 2;     // 0..1 (M half)
    const int ng   = wid & 3;      // 0..3 (N quarter)
    const int b    = blockIdx.x >> 6;

    float* ws_s  = reinterpret_cast<float*>(smem + SM_WS);
    float* V_s   = reinterpret_cast<float*>(smem + SM_V);
    float* en_s  = reinterpret_cast<float*>(smem + SM_EN);
    float* enf_s = reinterpret_cast<float*>(smem + SM_ENF);

    for (int i = tid; i < NDFF; i += 256) {
        ws_s[i] = g_ws[b * NDFF + i];
        V_s[i]  = V[i];
        en_s[i] = 0.f;
    }

    const float* hB = h + (size_t)blockIdx.x * (MTILE * KDIM);

    // ---- A stream mapping: thread -> (m = tid>>2, seg8 = tid&3) ----
    const int am   = tid >> 2;
    const int aseg = tid & 3;
    const uint32_t a_sts = SWZ((am >> 1) * 128 + (am & 1) * 64 + aseg * 16);
    const float4* aldg = reinterpret_cast<const float4*>(hB + am * KDIM + aseg * 8);

    // ---- B cp.async mapping: thread -> (f0 = tid>>2, seg8 = tid&3), 8 iters
    // iter adds f += 64 -> dst += 4096, src += 64*1024 halves ----
    const uint32_t b_dst0 = SWZ(((tid >> 2) >> 1) * 128 + ((tid >> 2) & 1) * 64 +
                                (tid & 3) * 16);
    const __half* b_src0 = g_Uh + (size_t)(tid >> 2) * KDIM + (tid & 3) * 8;

    // ---- ldmatrix offsets ----
    const int r = lane & 7;
    const int selA = (lane >> 3) & 1, selK = (lane >> 4) & 1;
    uint32_t aoffb[2];
    {
        int m0 = selA * 8 + r;
#pragma unroll
        for (int ki = 0; ki < 2; ki++)
            aoffb[ki] = SWZ((m0 >> 1) * 128 + (m0 & 1) * 64 +
                            (ki * 2 + selK) * 16) + mg * 2048;
    }
    const int selKb = (lane >> 3) & 1, selNb = (lane >> 4) & 1;
    uint32_t boffb[2];
    {
        int f0 = selNb * 8 + r;
#pragma unroll
        for (int ki = 0; ki < 2; ki++)
            boffb[ki] = SWZ((f0 >> 1) * 128 + (f0 & 1) * 64 +
                            (ki * 2 + selKb) * 16) + ng * 8192;
    }

    float acc[2][16][4];
#pragma unroll
    for (int mi = 0; mi < 2; mi++)
#pragma unroll
        for (int ni = 0; ni < 16; ni++)
#pragma unroll
            for (int q = 0; q < 4; q++) acc[mi][ni][q] = 0.f;

    float4 pa0, pa1;   // A fp32 staging

    // ---- prologue ----
    // A chunk 0 -> stage 0 ; A chunk 1 -> stage 1 ; A chunk 2 in regs
    {
        pa0 = aldg[0]; pa1 = aldg[1];
        uint4 u; __half2 t;
        t = __floats2half2_rn(pa0.x, pa0.y); u.x = *(uint32_t*)&t;
        t = __floats2half2_rn(pa0.z, pa0.w); u.y = *(uint32_t*)&t;
        t = __floats2half2_rn(pa1.x, pa1.y); u.z = *(uint32_t*)&t;
        t = __floats2half2_rn(pa1.z, pa1.w); u.w = *(uint32_t*)&t;
        *reinterpret_cast<uint4*>(smem + SM_A + a_sts) = u;
        pa0 = aldg[8]; pa1 = aldg[9];
        t = __floats2half2_rn(pa0.x, pa0.y); u.x = *(uint32_t*)&t;
        t = __floats2half2_rn(pa0.z, pa0.w); u.y = *(uint32_t*)&t;
        t = __floats2half2_rn(pa1.x, pa1.y); u.z = *(uint32_t*)&t;
        t = __floats2half2_rn(pa1.z, pa1.w); u.w = *(uint32_t*)&t;
        *reinterpret_cast<uint4*>(smem + SM_A + 4096 + a_sts) = u;
        pa0 = aldg[16]; pa1 = aldg[17];
    }
#pragma unroll
    for (int c = 0; c < 2; c++) {
        uint32_t dst = sb + SM_B + c * 32768 + b_dst0;
        const __half* src = b_src0 + c * KCH;
#pragma unroll
        for (int it = 0; it < 8; it++)
            cp_async16(dst + it * 4096, src + it * (64 * KDIM));
        CP_COMMIT();
    }

    // ---- K mainloop ----
#pragma unroll 1
    for (int c = 0; c < NCHUNKS; c++) {
        CP_WAIT1();
        __syncthreads();

        if (c + 2 < NCHUNKS) {
            const int st = (c + 2) % 3;
            // B chunk c+2
            uint32_t dst = sb + SM_B + st * 32768 + b_dst0;
            const __half* src = b_src0 + (c + 2) * KCH;
#pragma unroll
            for (int it = 0; it < 8; it++)
                cp_async16(dst + it * 4096, src + it * (64 * KDIM));
            // A chunk c+2 (from regs), then LDG chunk c+3
            uint4 u; __half2 t;
            t = __floats2half2_rn(pa0.x, pa0.y); u.x = *(uint32_t*)&t;
            t = __floats2half2_rn(pa0.z, pa0.w); u.y = *(uint32_t*)&t;
            t = __floats2half2_rn(pa1.x, pa1.y); u.z = *(uint32_t*)&t;
            t = __floats2half2_rn(pa1.z, pa1.w); u.w = *(uint32_t*)&t;
            *reinterpret_cast<uint4*>(smem + SM_A + st * 4096 + a_sts) = u;
            if (c + 3 < NCHUNKS) {
                pa0 = aldg[(c + 3) * 8];
                pa1 = aldg[(c + 3) * 8 + 1];
            }
        }
        CP_COMMIT();

        const uint32_t ab = sb + SM_A + (c % 3) * 4096;
        const uint32_t bb = sb + SM_B + (c % 3) * 32768;
#pragma unroll
        for (int ki = 0; ki < 2; ki++) {
            uint32_t a00, a01, a02, a03, a10, a11, a12, a13;
            ldsm4(a00, a01, a02, a03, ab + aoffb[ki]);
            ldsm4(a10, a11, a12, a13, ab + aoffb[ki] + 1024);
#pragma unroll
            for (int j = 0; j < 8; j++) {
                uint32_t b0, b1, b2, b3;
                ldsm4(b0, b1, b2, b3, bb + boffb[ki] + j * 1024);
                mma16816(acc[0][2 * j],     a00, a01, a02, a03, b0, b1);
                mma16816(acc[0][2 * j + 1], a00, a01, a02, a03, b2, b3);
                mma16816(acc[1][2 * j],     a10, a11, a12, a13, b0, b1);
                mma16816(acc[1][2 * j + 1], a10, a11, a12, a13, b2, b3);
            }
        }
    }

    // ---- epilogue: energy[m] = Vb + sum_f V[f] * tanh(ws[f] + uh[m,f]) ----
#pragma unroll
    for (int mi = 0; mi < 2; mi++) {
#pragma unroll
        for (int rh = 0; rh < 2; rh++) {
            float s = 0.f;
#pragma unroll
            for (int ni = 0; ni < 16; ni++) {
#pragma unroll
                for (int q = 0; q < 2; q++) {
                    int f = ng * 128 + ni * 8 + ((lane & 3) << 1) + q;
                    float z = ws_s[f] + acc[mi][ni][rh * 2 + q];
                    z = fminf(fmaxf(z, -15.f), 15.f);
                    float e2 = __expf(2.f * z);
                    float x = __fdividef(e2 - 1.f, e2 + 1.f);
                    s = fmaf(V_s[f], x, s);
                }
            }
            s += __shfl_xor_sync(0xffffffffu, s, 1);
            s += __shfl_xor_sync(0xffffffffu, s, 2);
            if ((lane & 3) == 0)
                en_s[(wid << 6) + mg * 32 + mi * 16 + rh * 8 + (lane >> 2)] = s;
        }
    }
    __syncthreads();
    if (tid < MTILE) {
        float e = Vb[0];
#pragma unroll
        for (int w = 0; w < 8; w++) e += en_s[(w << 6) + tid];
        enf_s[tid] = e;
    }
    __syncthreads();

    // ---- context partial: sum_m energy[m] * h[m, e] (fp32 from gmem/L2) ----
    {
        const float4* h4 = reinterpret_cast<const float4*>(hB);
        float a0 = 0.f, a1 = 0.f, a2 = 0.f, a3 = 0.f;
#pragma unroll 8
        for (int m = 0; m < MTILE; m++) {
            float en = enf_s[m];
            float4 hv = h4[m * 256 + tid];
            a0 = fmaf(en, hv.x, a0);
            a1 = fmaf(en, hv.y, a1);
            a2 = fmaf(en, hv.z, a2);
            a3 = fmaf(en, hv.w, a3);
        }
        float4 o = make_float4(a0, a1, a2, a3);
        reinterpret_cast<float4*>(g_partial)[((size_t)blockIdx.x << 8) + tid] = o;
    }
}

// ---------------------------------------------------------------------------
extern "C" void kernel_launch(void* const* d_in, const int* in_sizes, int n_in,
                              void* d_out, int out_size) {
    (void)in_sizes; (void)n_in; (void)out_size;
    const float* s  = (const float*)d_in[0];
    const float* h  = (const float*)d_in[1];
    const float* Ww = (const float*)d_in[2];
    const float* Wb = (const float*)d_in[3];
    const float* Uw = (const float*)d_in[4];
    const float* Ub = (const float*)d_in[5];
    const float* Vw = (const float*)d_in[6];
    const float* Vb = (const float*)d_in[7];
    float* out = (float*)d_out;

    cudaFuncSetAttribute(k_main, cudaFuncAttributeMaxDynamicSharedMemorySize,
                         SMEM_TOTAL);

    k_convU<<<512, 256>>>((const float4*)Uw);
    k_ws<<<BATCH, 512>>>(s, Ww, Wb, Ub);
    k_main<<<NCTAS, 256, SMEM_TOTAL>>>(h, Vw, Vb);
    k_reduce<<<128, 256>>>(out);
}

// round 5
// speedup vs baseline: 1.4403x; 1.1491x over previous
#include <cuda_runtime.h>
#include <cuda_fp16.h>
#include <cstdint>

// ---------------------------------------------------------------------------
// B=32, T=4096, K=1024 (2H), N=512 (DFF)
// HMMA GEMM, 2 CTAs/SM: warp tile M32 x N64, 2 N-passes of 256, K-chunk 32.
// Fused tanh/V epilogue -> energy, context contraction, in-kernel final reduce.
// ---------------------------------------------------------------------------
#define BATCH   32
#define TSEQ    4096
#define KDIM    1024
#define NDFF    512
#define MTILE   64
#define KCH     32
#define NCHUNKS 32
#define NTILES  (TSEQ / MTILE)     // 64
#define NCTAS   (BATCH * NTILES)   // 2048

__device__ __align__(128) __half g_Uh[NDFF * KDIM];             // 1 MB fp16 U [f][e]
__device__ __align__(128) float  g_ws[BATCH * NDFF];
__device__ __align__(128) float  g_partial[NCTAS * KDIM];       // 8 MB
__device__ int g_cnt[BATCH];

// Shared layout (bytes)
#define SM_WS   0                       // 512 f
#define SM_V    2048                    // 512 f
#define SM_EN   4096                    // 8*64 f
#define SM_ENF  6144                    // 64 f
#define SM_FLAG 6400                    // int
#define SM_A    8192                    // 3 stages x 4096
#define SM_B    20480                   // 3 stages x 16384
#define SMEM_TOTAL 69632

#define SWZ(off) ((uint32_t)(off) ^ ((((uint32_t)(off)) >> 3) & 0x70u))

__device__ __forceinline__ uint32_t smem_u32(const void* p) {
    uint32_t a;
    asm("{ .reg .u64 t; cvta.to.shared.u64 t, %1; cvt.u32.u64 %0, t; }"
        : "=r"(a) : "l"(p));
    return a;
}
__device__ __forceinline__ void cp_async16(uint32_t dst, const void* src) {
    asm volatile("cp.async.cg.shared.global [%0], [%1], 16;"
                 :: "r"(dst), "l"(src) : "memory");
}
#define CP_COMMIT() asm volatile("cp.async.commit_group;" ::: "memory")
#define CP_WAIT1()  asm volatile("cp.async.wait_group 1;" ::: "memory")

__device__ __forceinline__ void ldsm4(uint32_t& r0, uint32_t& r1, uint32_t& r2,
                                      uint32_t& r3, uint32_t addr) {
    asm volatile("ldmatrix.sync.aligned.m8n8.x4.shared.b16 {%0,%1,%2,%3}, [%4];"
                 : "=r"(r0), "=r"(r1), "=r"(r2), "=r"(r3) : "r"(addr));
}
__device__ __forceinline__ void mma16816(float* c, uint32_t a0, uint32_t a1,
                                         uint32_t a2, uint32_t a3,
                                         uint32_t b0, uint32_t b1) {
    asm volatile(
        "mma.sync.aligned.m16n8k16.row.col.f32.f16.f16.f32 "
        "{%0,%1,%2,%3}, {%4,%5,%6,%7}, {%8,%9}, {%0,%1,%2,%3};"
        : "+f"(c[0]), "+f"(c[1]), "+f"(c[2]), "+f"(c[3])
        : "r"(a0), "r"(a1), "r"(a2), "r"(a3), "r"(b0), "r"(b1));
}

// ---------------------------------------------------------------------------
// Fused prep: blocks 0..511 convU, 512..575 ws, 576 zero counters
// ---------------------------------------------------------------------------
__global__ void k_prep(const float* __restrict__ Uw, const float* __restrict__ s,
                       const float* __restrict__ W,  const float* __restrict__ Wb,
                       const float* __restrict__ Ub) {
    int blk = blockIdx.x;
    int tid = threadIdx.x;
    if (blk < 512) {
        int i = blk * 256 + tid;
        float4 v = reinterpret_cast<const float4*>(Uw)[i];
        __half2 p0 = __floats2half2_rn(v.x, v.y);
        __half2 p1 = __floats2half2_rn(v.z, v.w);
        uint2 u;
        u.x = *reinterpret_cast<uint32_t*>(&p0);
        u.y = *reinterpret_cast<uint32_t*>(&p1);
        *reinterpret_cast<uint2*>(&g_Uh[i * 4]) = u;
    } else if (blk < 576) {
        __shared__ float ssh[512];
        int q = blk - 512;
        int b = q >> 1;
        int f = ((q & 1) << 8) + tid;
        ssh[tid]       = s[b * 512 + tid];
        ssh[tid + 256] = s[b * 512 + tid + 256];
        __syncthreads();
        float acc = Wb[f] + Ub[f];
        const float4* Wr = reinterpret_cast<const float4*>(W + (size_t)f * 512);
#pragma unroll 4
        for (int e4 = 0; e4 < 128; e4++) {
            float4 w = Wr[e4];
            acc = fmaf(ssh[e4 * 4 + 0], w.x, acc);
            acc = fmaf(ssh[e4 * 4 + 1], w.y, acc);
            acc = fmaf(ssh[e4 * 4 + 2], w.z, acc);
            acc = fmaf(ssh[e4 * 4 + 3], w.w, acc);
        }
        g_ws[b * 512 + f] = acc;
    } else {
        if (tid < BATCH) g_cnt[tid] = 0;
    }
}

// ---------------------------------------------------------------------------
// Main kernel: 256 threads, 8 warps = 2(M) x 4(N), warp tile M32 x N64.
// Packed smem rows: two 64B k-rows per 128B smem row, SW128-swizzled.
// ---------------------------------------------------------------------------
__global__ __launch_bounds__(256, 2)
void k_main(const float* __restrict__ h, const float* __restrict__ V,
            const float* __restrict__ Vb, float* __restrict__ out) {
    extern __shared__ char smem[];
    const uint32_t sb = smem_u32(smem);
    const int tid  = threadIdx.x;
    const int wid  = tid >> 5;
    const int lane = tid & 31;
    const int mg   = wid >> 2;     // 0..1
    const int ng   = wid & 3;      // 0..3
    const int b    = blockIdx.x >> 6;

    float* ws_s  = reinterpret_cast<float*>(smem + SM_WS);
    float* V_s   = reinterpret_cast<float*>(smem + SM_V);
    float* en_s  = reinterpret_cast<float*>(smem + SM_EN);
    float* enf_s = reinterpret_cast<float*>(smem + SM_ENF);
    int*   flag  = reinterpret_cast<int*>(smem + SM_FLAG);

    for (int i = tid; i < NDFF; i += 256) {
        ws_s[i] = g_ws[b * NDFF + i];
        V_s[i]  = V[i];
        en_s[i] = 0.f;
    }

    const float* hB = h + (size_t)blockIdx.x * (MTILE * KDIM);

    // A stream map: thread -> (m = tid>>2, seg = tid&3)
    const int am = tid >> 2, aseg = tid & 3;
    const uint32_t a_sts = SWZ((am >> 1) * 128 + (am & 1) * 64 + aseg * 16);
    const float4* aldg = reinterpret_cast<const float4*>(hB + am * KDIM + aseg * 8);

    // B cp.async map: it in 0..3, idx = it*256+tid -> row=idx>>2, seg=idx&3
    uint32_t bdst[4];
    uint32_t bsrcoff[4];               // in halves
#pragma unroll
    for (int it = 0; it < 4; it++) {
        int idx = it * 256 + tid;
        int row = idx >> 2, seg = idx & 3;
        bdst[it]    = SWZ((row >> 1) * 128 + (row & 1) * 64 + seg * 16);
        bsrcoff[it] = row * KDIM + seg * 8;
    }

    // ldsm offsets
    const int r = lane & 7;
    const int selA = (lane >> 3) & 1, selK = (lane >> 4) & 1;
    uint32_t aoffb[2];
    {
        int m0 = selA * 8 + r;
#pragma unroll
        for (int ki = 0; ki < 2; ki++)
            aoffb[ki] = SWZ((m0 >> 1) * 128 + (m0 & 1) * 64 +
                            (ki * 2 + selK) * 16) + mg * 2048;
    }
    const int selKb = (lane >> 3) & 1, selNb = (lane >> 4) & 1;
    uint32_t boffb[2];
    {
        int f0 = selNb * 8 + r;
#pragma unroll
        for (int ki = 0; ki < 2; ki++)
            boffb[ki] = SWZ((f0 >> 1) * 128 + (f0 & 1) * 64 +
                            (ki * 2 + selKb) * 16) + ng * 4096;
    }

    float4 pa0, pa1;

    // ======================= two N-passes of 256 =======================
#pragma unroll 1
    for (int np = 0; np < 2; np++) {
        const __half* Ub2 = g_Uh + (size_t)(np * 256) * KDIM;

        float acc[2][8][4];
#pragma unroll
        for (int mi = 0; mi < 2; mi++)
#pragma unroll
            for (int ni = 0; ni < 8; ni++)
#pragma unroll
                for (int q = 0; q < 4; q++) acc[mi][ni][q] = 0.f;

        __syncthreads();   // stage ring reuse safe across passes

        // prologue: A chunks 0,1 -> stages 0,1; chunk 2 in regs; B chunks 0,1
        {
            pa0 = aldg[0]; pa1 = aldg[1];
            uint4 u; __half2 t;
            t = __floats2half2_rn(pa0.x, pa0.y); u.x = *(uint32_t*)&t;
            t = __floats2half2_rn(pa0.z, pa0.w); u.y = *(uint32_t*)&t;
            t = __floats2half2_rn(pa1.x, pa1.y); u.z = *(uint32_t*)&t;
            t = __floats2half2_rn(pa1.z, pa1.w); u.w = *(uint32_t*)&t;
            *reinterpret_cast<uint4*>(smem + SM_A + a_sts) = u;
            pa0 = aldg[8]; pa1 = aldg[9];
            t = __floats2half2_rn(pa0.x, pa0.y); u.x = *(uint32_t*)&t;
            t = __floats2half2_rn(pa0.z, pa0.w); u.y = *(uint32_t*)&t;
            t = __floats2half2_rn(pa1.x, pa1.y); u.z = *(uint32_t*)&t;
            t = __floats2half2_rn(pa1.z, pa1.w); u.w = *(uint32_t*)&t;
            *reinterpret_cast<uint4*>(smem + SM_A + 4096 + a_sts) = u;
            pa0 = aldg[16]; pa1 = aldg[17];
        }
#pragma unroll
        for (int c = 0; c < 2; c++) {
            uint32_t dst = sb + SM_B + c * 16384;
            const __half* src = Ub2 + c * KCH;
#pragma unroll
            for (int it = 0; it < 4; it++)
                cp_async16(dst + bdst[it], src + bsrcoff[it]);
            CP_COMMIT();
        }

        // ---------------- K mainloop ----------------
#pragma unroll 1
        for (int c = 0; c < NCHUNKS; c++) {
            CP_WAIT1();
            __syncthreads();

            if (c + 2 < NCHUNKS) {
                const int st = (c + 2) % 3;
                uint32_t dst = sb + SM_B + st * 16384;
                const __half* src = Ub2 + (c + 2) * KCH;
#pragma unroll
                for (int it = 0; it < 4; it++)
                    cp_async16(dst + bdst[it], src + bsrcoff[it]);
                uint4 u; __half2 t;
                t = __floats2half2_rn(pa0.x, pa0.y); u.x = *(uint32_t*)&t;
                t = __floats2half2_rn(pa0.z, pa0.w); u.y = *(uint32_t*)&t;
                t = __floats2half2_rn(pa1.x, pa1.y); u.z = *(uint32_t*)&t;
                t = __floats2half2_rn(pa1.z, pa1.w); u.w = *(uint32_t*)&t;
                *reinterpret_cast<uint4*>(smem + SM_A + st * 4096 + a_sts) = u;
                if (c + 3 < NCHUNKS) {
                    pa0 = aldg[(c + 3) * 8];
                    pa1 = aldg[(c + 3) * 8 + 1];
                }
            }
            CP_COMMIT();

            const uint32_t ab = sb + SM_A + (c % 3) * 4096;
            const uint32_t bb = sb + SM_B + (c % 3) * 16384;
#pragma unroll
            for (int ki = 0; ki < 2; ki++) {
                uint32_t a00, a01, a02, a03, a10, a11, a12, a13;
                ldsm4(a00, a01, a02, a03, ab + aoffb[ki]);
                ldsm4(a10, a11, a12, a13, ab + aoffb[ki] + 1024);
#pragma unroll
                for (int j = 0; j < 4; j++) {
                    uint32_t b0, b1, b2, b3;
                    ldsm4(b0, b1, b2, b3, bb + boffb[ki] + j * 1024);
                    mma16816(acc[0][2 * j],     a00, a01, a02, a03, b0, b1);
                    mma16816(acc[0][2 * j + 1], a00, a01, a02, a03, b2, b3);
                    mma16816(acc[1][2 * j],     a10, a11, a12, a13, b0, b1);
                    mma16816(acc[1][2 * j + 1], a10, a11, a12, a13, b2, b3);
                }
            }
        }

        // ---------------- epilogue: energy partials ----------------
#pragma unroll
        for (int mi = 0; mi < 2; mi++) {
#pragma unroll
            for (int rh = 0; rh < 2; rh++) {
                float s = 0.f;
#pragma unroll
                for (int ni = 0; ni < 8; ni++) {
#pragma unroll
                    for (int q = 0; q < 2; q++) {
                        int f = np * 256 + ng * 64 + ni * 8 + ((lane & 3) << 1) + q;
                        float z = ws_s[f] + acc[mi][ni][rh * 2 + q];
                        z = fminf(fmaxf(z, -15.f), 15.f);
                        float e2 = __expf(2.f * z);
                        float x = __fdividef(e2 - 1.f, e2 + 1.f);
                        s = fmaf(V_s[f], x, s);
                    }
                }
                s += __shfl_xor_sync(0xffffffffu, s, 1);
                s += __shfl_xor_sync(0xffffffffu, s, 2);
                if ((lane & 3) == 0)
                    en_s[(wid << 6) + mg * 32 + mi * 16 + rh * 8 + (lane >> 2)] += s;
            }
        }
    }

    // ---------------- finalize energy ----------------
    __syncthreads();
    if (tid < MTILE) {
        float e = Vb[0];
#pragma unroll
        for (int w = 0; w < 8; w++) e += en_s[(w << 6) + tid];
        enf_s[tid] = e;
    }
    __syncthreads();

    // ---------------- context partial: sum_m energy[m] * h[m, e] ----------------
    {
        const float4* h4 = reinterpret_cast<const float4*>(hB);
        float a0 = 0.f, a1 = 0.f, a2 = 0.f, a3 = 0.f;
#pragma unroll 8
        for (int m = 0; m < MTILE; m++) {
            float en = enf_s[m];
            float4 hv = h4[m * 256 + tid];
            a0 = fmaf(en, hv.x, a0);
            a1 = fmaf(en, hv.y, a1);
            a2 = fmaf(en, hv.z, a2);
            a3 = fmaf(en, hv.w, a3);
        }
        float4 o = make_float4(a0, a1, a2, a3);
        reinterpret_cast<float4*>(g_partial)[((size_t)blockIdx.x << 8) + tid] = o;
    }

    // ---------------- last CTA per batch reduces (deterministic order) --------
    __threadfence();
    if (tid == 0) {
        int old = atomicAdd(&g_cnt[b], 1);
        *flag = (old == NTILES - 1) ? 1 : 0;
    }
    __syncthreads();
    if (*flag) {
        __threadfence();
        const float4* gp = reinterpret_cast<const float4*>(
            g_partial + ((size_t)b * NTILES) * KDIM);
        float4 acc = make_float4(0.f, 0.f, 0.f, 0.f);
#pragma unroll 8
        for (int tt = 0; tt < NTILES; tt++) {
            float4 v = gp[tt * 256 + tid];
            acc.x += v.x; acc.y += v.y; acc.z += v.z; acc.w += v.w;
        }
        reinterpret_cast<float4*>(out)[b * 256 + tid] = acc;
    }
}

// ---------------------------------------------------------------------------
extern "C" void kernel_launch(void* const* d_in, const int* in_sizes, int n_in,
                              void* d_out, int out_size) {
    (void)in_sizes; (void)n_in; (void)out_size;
    const float* s  = (const float*)d_in[0];
    const float* h  = (const float*)d_in[1];
    const float* Ww = (const float*)d_in[2];
    const float* Wb = (const float*)d_in[3];
    const float* Uw = (const float*)d_in[4];
    const float* Ub = (const float*)d_in[5];
    const float* Vw = (const float*)d_in[6];
    const float* Vb = (const float*)d_in[7];
    float* out = (float*)d_out;

    cudaFuncSetAttribute(k_main, cudaFuncAttributeMaxDynamicSharedMemorySize,
                         SMEM_TOTAL);

    k_prep<<<577, 256>>>(Uw, s, Ww, Wb, Ub);
    k_main<<<NCTAS, 256, SMEM_TOTAL>>>(h, Vw, Vb, out);
}

// round 6
// speedup vs baseline: 1.5893x; 1.1034x over previous
#include <cuda_runtime.h>
#include <cuda_fp16.h>
#include <cstdint>

// ---------------------------------------------------------------------------
// B=32, T=4096, K=1024 (2H), N=512 (DFF)
// HMMA GEMM, 2 CTAs/SM, 128 threads: warp tile M64 x N64, 2 N-passes of 256.
// ---------------------------------------------------------------------------
#define BATCH   32
#define TSEQ    4096
#define KDIM    1024
#define NDFF    512
#define MTILE   64
#define KCH     32
#define NCHUNKS 32
#define NTILES  (TSEQ / MTILE)     // 64
#define NCTAS   (BATCH * NTILES)   // 2048

__device__ __align__(128) __half g_Uh[NDFF * KDIM];             // 1 MB fp16 U [f][e]
__device__ __align__(128) float  g_ws[BATCH * NDFF];
__device__ __align__(128) float  g_partial[NCTAS * KDIM];       // 8 MB
__device__ int g_cnt[BATCH];

// Shared layout (bytes)
#define SM_WS   0                       // 512 f
#define SM_V    2048                    // 512 f
#define SM_EN   4096                    // 4*64 f
#define SM_ENF  5120                    // 64 f
#define SM_FLAG 5376                    // int
#define SM_A    8192                    // 3 stages x 4096
#define SM_B    20480                   // 3 stages x 16384
#define SMEM_TOTAL 69632

#define SWZ(off) ((uint32_t)(off) ^ ((((uint32_t)(off)) >> 3) & 0x70u))

__device__ __forceinline__ uint32_t smem_u32(const void* p) {
    uint32_t a;
    asm("{ .reg .u64 t; cvta.to.shared.u64 t, %1; cvt.u32.u64 %0, t; }"
        : "=r"(a) : "l"(p));
    return a;
}
__device__ __forceinline__ void cp_async16(uint32_t dst, const void* src) {
    asm volatile("cp.async.cg.shared.global [%0], [%1], 16;"
                 :: "r"(dst), "l"(src) : "memory");
}
#define CP_COMMIT() asm volatile("cp.async.commit_group;" ::: "memory")
#define CP_WAIT1()  asm volatile("cp.async.wait_group 1;" ::: "memory")

__device__ __forceinline__ void ldsm4(uint32_t& r0, uint32_t& r1, uint32_t& r2,
                                      uint32_t& r3, uint32_t addr) {
    asm volatile("ldmatrix.sync.aligned.m8n8.x4.shared.b16 {%0,%1,%2,%3}, [%4];"
                 : "=r"(r0), "=r"(r1), "=r"(r2), "=r"(r3) : "r"(addr));
}
__device__ __forceinline__ void mma16816(float* c, const uint32_t* a,
                                         uint32_t b0, uint32_t b1) {
    asm volatile(
        "mma.sync.aligned.m16n8k16.row.col.f32.f16.f16.f32 "
        "{%0,%1,%2,%3}, {%4,%5,%6,%7}, {%8,%9}, {%0,%1,%2,%3};"
        : "+f"(c[0]), "+f"(c[1]), "+f"(c[2]), "+f"(c[3])
        : "r"(a[0]), "r"(a[1]), "r"(a[2]), "r"(a[3]), "r"(b0), "r"(b1));
}
__device__ __forceinline__ uint4 cvt8(const float4& x, const float4& y) {
    uint4 u; __half2 t;
    t = __floats2half2_rn(x.x, x.y); u.x = *(uint32_t*)&t;
    t = __floats2half2_rn(x.z, x.w); u.y = *(uint32_t*)&t;
    t = __floats2half2_rn(y.x, y.y); u.z = *(uint32_t*)&t;
    t = __floats2half2_rn(y.z, y.w); u.w = *(uint32_t*)&t;
    return u;
}

// ---------------------------------------------------------------------------
// Fused prep: blocks 0..511 convU, 512..575 ws, 576 zero counters
// ---------------------------------------------------------------------------
__global__ void k_prep(const float* __restrict__ Uw, const float* __restrict__ s,
                       const float* __restrict__ W,  const float* __restrict__ Wb,
                       const float* __restrict__ Ub) {
    int blk = blockIdx.x;
    int tid = threadIdx.x;
    if (blk < 512) {
        int i = blk * 256 + tid;
        float4 v = reinterpret_cast<const float4*>(Uw)[i];
        __half2 p0 = __floats2half2_rn(v.x, v.y);
        __half2 p1 = __floats2half2_rn(v.z, v.w);
        uint2 u;
        u.x = *reinterpret_cast<uint32_t*>(&p0);
        u.y = *reinterpret_cast<uint32_t*>(&p1);
        *reinterpret_cast<uint2*>(&g_Uh[i * 4]) = u;
    } else if (blk < 576) {
        __shared__ float ssh[512];
        int q = blk - 512;
        int b = q >> 1;
        int f = ((q & 1) << 8) + tid;
        ssh[tid]       = s[b * 512 + tid];
        ssh[tid + 256] = s[b * 512 + tid + 256];
        __syncthreads();
        float acc = Wb[f] + Ub[f];
        const float4* Wr = reinterpret_cast<const float4*>(W + (size_t)f * 512);
#pragma unroll 4
        for (int e4 = 0; e4 < 128; e4++) {
            float4 w = Wr[e4];
            acc = fmaf(ssh[e4 * 4 + 0], w.x, acc);
            acc = fmaf(ssh[e4 * 4 + 1], w.y, acc);
            acc = fmaf(ssh[e4 * 4 + 2], w.z, acc);
            acc = fmaf(ssh[e4 * 4 + 3], w.w, acc);
        }
        g_ws[b * 512 + f] = acc;
    } else {
        if (tid < BATCH) g_cnt[tid] = 0;
    }
}

// ---------------------------------------------------------------------------
// Main kernel: 128 threads, 4 warps, warp tile M64 x N64, 2 CTAs/SM.
// Packed smem rows: two 64B k-rows per 128B smem row, SW128-swizzled.
// ---------------------------------------------------------------------------
__global__ __launch_bounds__(128, 2)
void k_main(const float* __restrict__ h, const float* __restrict__ V,
            const float* __restrict__ Vb, float* __restrict__ out) {
    extern __shared__ char smem[];
    const uint32_t sb = smem_u32(smem);
    const int tid  = threadIdx.x;
    const int wid  = tid >> 5;     // = ng, 0..3
    const int lane = tid & 31;
    const int b    = blockIdx.x >> 6;

    float* ws_s  = reinterpret_cast<float*>(smem + SM_WS);
    float* V_s   = reinterpret_cast<float*>(smem + SM_V);
    float* en_s  = reinterpret_cast<float*>(smem + SM_EN);
    float* enf_s = reinterpret_cast<float*>(smem + SM_ENF);
    int*   flag  = reinterpret_cast<int*>(smem + SM_FLAG);

    for (int i = tid; i < NDFF; i += 128) {
        ws_s[i] = g_ws[b * NDFF + i];
        V_s[i]  = V[i];
    }
    for (int i = tid; i < 4 * MTILE; i += 128) en_s[i] = 0.f;

    const float* hB = h + (size_t)blockIdx.x * (MTILE * KDIM);

    // ---- A stream map: idx = it*128+tid -> m = idx>>2 (it adds 32), seg = tid&3
    const int m_0 = tid >> 2, seg = tid & 3;
    const uint32_t a_sts0 = SWZ((m_0 >> 1) * 128 + (m_0 & 1) * 64 + seg * 16);
    const float4* ap0 = reinterpret_cast<const float4*>(hB) + m_0 * 256 + seg * 2;
    const float4* ap1 = ap0 + 32 * 256;       // rows +32 ; smem +2048 (swizzle-safe)

    // ---- B cp.async map: idx = it*128+tid -> row = it*32 + (tid>>2), seg
    const uint32_t bdst0 = a_sts0;             // same formula for row0 = tid>>2
    const uint32_t bsrc0 = (uint32_t)(m_0 * KDIM + seg * 8);   // halves

    // ---- ldsm bases (XOR-incremental) ----
    const int r = lane & 7;
    const int selA = (lane >> 3) & 1, selK = (lane >> 4) & 1;
    const int m0f = selA * 8 + r;
    const uint32_t abase0 = SWZ((m0f >> 1) * 128 + (m0f & 1) * 64 + selK * 16);
    const int selKb = (lane >> 3) & 1, selNb = (lane >> 4) & 1;
    const int f0f = selNb * 8 + r;
    const uint32_t bbase0 = SWZ((f0f >> 1) * 128 + (f0f & 1) * 64 + selKb * 16)
                            + (uint32_t)wid * 4096;

    float4 p00, p01, p10, p11;

    // ======================= two N-passes of 256 =======================
#pragma unroll 1
    for (int np = 0; np < 2; np++) {
        const __half* Ub2 = g_Uh + (size_t)(np * 256) * KDIM;

        float acc[4][8][4];
#pragma unroll
        for (int mi = 0; mi < 4; mi++)
#pragma unroll
            for (int ni = 0; ni < 8; ni++)
#pragma unroll
                for (int q = 0; q < 4; q++) acc[mi][ni][q] = 0.f;

        __syncthreads();

        // prologue: A chunks 0,1 -> stages 0,1; chunk 2 in regs; B chunks 0,1
        p00 = ap0[0];  p01 = ap0[1];  p10 = ap1[0];  p11 = ap1[1];
        *reinterpret_cast<uint4*>(smem + SM_A + a_sts0)        = cvt8(p00, p01);
        *reinterpret_cast<uint4*>(smem + SM_A + a_sts0 + 2048) = cvt8(p10, p11);
        p00 = ap0[8];  p01 = ap0[9];  p10 = ap1[8];  p11 = ap1[9];
        *reinterpret_cast<uint4*>(smem + SM_A + 4096 + a_sts0)        = cvt8(p00, p01);
        *reinterpret_cast<uint4*>(smem + SM_A + 4096 + a_sts0 + 2048) = cvt8(p10, p11);
        p00 = ap0[16]; p01 = ap0[17]; p10 = ap1[16]; p11 = ap1[17];
#pragma unroll
        for (int c = 0; c < 2; c++) {
            uint32_t dst = sb + SM_B + c * 16384 + bdst0;
            const __half* src = Ub2 + bsrc0 + c * KCH;
#pragma unroll
            for (int it = 0; it < 8; it++)
                cp_async16(dst + it * 2048, src + it * (32 * KDIM));
            CP_COMMIT();
        }

        // ---------------- K mainloop ----------------
#pragma unroll 1
        for (int c = 0; c < NCHUNKS; c++) {
            CP_WAIT1();
            __syncthreads();

            if (c + 2 < NCHUNKS) {
                const int st = (c + 2) % 3;
                uint32_t dst = sb + SM_B + st * 16384 + bdst0;
                const __half* src = Ub2 + bsrc0 + (c + 2) * KCH;
#pragma unroll
                for (int it = 0; it < 8; it++)
                    cp_async16(dst + it * 2048, src + it * (32 * KDIM));
                *reinterpret_cast<uint4*>(smem + SM_A + st * 4096 + a_sts0)
                    = cvt8(p00, p01);
                *reinterpret_cast<uint4*>(smem + SM_A + st * 4096 + a_sts0 + 2048)
                    = cvt8(p10, p11);
                if (c + 3 < NCHUNKS) {
                    p00 = ap0[(c + 3) * 8];     p01 = ap0[(c + 3) * 8 + 1];
                    p10 = ap1[(c + 3) * 8];     p11 = ap1[(c + 3) * 8 + 1];
                }
            }
            CP_COMMIT();

            const uint32_t ab = sb + SM_A + (c % 3) * 4096;
            const uint32_t bb = sb + SM_B + (c % 3) * 16384;
#pragma unroll
            for (int ki = 0; ki < 2; ki++) {
                const uint32_t kx = (uint32_t)ki * 32;
                uint32_t af[4][4];
#pragma unroll
                for (int mi = 0; mi < 4; mi++)
                    ldsm4(af[mi][0], af[mi][1], af[mi][2], af[mi][3],
                          ab + ((abase0 + mi * 1024) ^ kx));
#pragma unroll
                for (int nj = 0; nj < 4; nj++) {
                    uint32_t b0, b1, b2, b3;
                    ldsm4(b0, b1, b2, b3, bb + ((bbase0 + nj * 1024) ^ kx));
#pragma unroll
                    for (int mi = 0; mi < 4; mi++) {
                        mma16816(acc[mi][2 * nj],     af[mi], b0, b1);
                        mma16816(acc[mi][2 * nj + 1], af[mi], b2, b3);
                    }
                }
            }
        }

        // ---------------- epilogue: energy partials ----------------
#pragma unroll
        for (int mi = 0; mi < 4; mi++) {
#pragma unroll
            for (int rh = 0; rh < 2; rh++) {
                float s = 0.f;
#pragma unroll
                for (int nj = 0; nj < 4; nj++) {
#pragma unroll
                    for (int jj = 0; jj < 2; jj++) {
#pragma unroll
                        for (int q = 0; q < 2; q++) {
                            int f = np * 256 + wid * 64 + nj * 16 + jj * 8 +
                                    ((lane & 3) << 1) + q;
                            float z = ws_s[f] + acc[mi][nj * 2 + jj][rh * 2 + q];
                            z = fminf(fmaxf(z, -15.f), 15.f);
                            float e2 = __expf(2.f * z);
                            float x = __fdividef(e2 - 1.f, e2 + 1.f);
                            s = fmaf(V_s[f], x, s);
                        }
                    }
                }
                s += __shfl_xor_sync(0xffffffffu, s, 1);
                s += __shfl_xor_sync(0xffffffffu, s, 2);
                if ((lane & 3) == 0)
                    en_s[(wid << 6) + mi * 16 + rh * 8 + (lane >> 2)] += s;
            }
        }
    }

    // ---------------- finalize energy ----------------
    __syncthreads();
    if (tid < MTILE) {
        float e = Vb[0];
#pragma unroll
        for (int w = 0; w < 4; w++) e += en_s[(w << 6) + tid];
        enf_s[tid] = e;
    }
    __syncthreads();

    // ---------------- context partial: sum_m energy[m] * h[m, e] --------------
    {
        const float4* h4 = reinterpret_cast<const float4*>(hB);
        float4 a0 = make_float4(0.f, 0.f, 0.f, 0.f);
        float4 a1 = make_float4(0.f, 0.f, 0.f, 0.f);
#pragma unroll 8
        for (int m = 0; m < MTILE; m++) {
            float en = enf_s[m];
            float4 v0 = h4[m * 256 + tid * 2];
            float4 v1 = h4[m * 256 + tid * 2 + 1];
            a0.x = fmaf(en, v0.x, a0.x); a0.y = fmaf(en, v0.y, a0.y);
            a0.z = fmaf(en, v0.z, a0.z); a0.w = fmaf(en, v0.w, a0.w);
            a1.x = fmaf(en, v1.x, a1.x); a1.y = fmaf(en, v1.y, a1.y);
            a1.z = fmaf(en, v1.z, a1.z); a1.w = fmaf(en, v1.w, a1.w);
        }
        float4* gp = reinterpret_cast<float4*>(g_partial) +
                     ((size_t)blockIdx.x << 8);
        gp[tid * 2]     = a0;
        gp[tid * 2 + 1] = a1;
    }

    // ---------------- last CTA per batch reduces (deterministic order) --------
    __threadfence();
    if (tid == 0) {
        int old = atomicAdd(&g_cnt[b], 1);
        *flag = (old == NTILES - 1) ? 1 : 0;
    }
    __syncthreads();
    if (*flag) {
        __threadfence();
        const float4* gp = reinterpret_cast<const float4*>(
            g_partial + ((size_t)b * NTILES) * KDIM);
        float4 a0 = make_float4(0.f, 0.f, 0.f, 0.f);
        float4 a1 = make_float4(0.f, 0.f, 0.f, 0.f);
#pragma unroll 8
        for (int tt = 0; tt < NTILES; tt++) {
            float4 v0 = gp[tt * 256 + tid * 2];
            float4 v1 = gp[tt * 256 + tid * 2 + 1];
            a0.x += v0.x; a0.y += v0.y; a0.z += v0.z; a0.w += v0.w;
            a1.x += v1.x; a1.y += v1.y; a1.z += v1.z; a1.w += v1.w;
        }
        float4* o4 = reinterpret_cast<float4*>(out) + b * 256;
        o4[tid * 2]     = a0;
        o4[tid * 2 + 1] = a1;
    }
}

// ---------------------------------------------------------------------------
extern "C" void kernel_launch(void* const* d_in, const int* in_sizes, int n_in,
                              void* d_out, int out_size) {
    (void)in_sizes; (void)n_in; (void)out_size;
    const float* s  = (const float*)d_in[0];
    const float* h  = (const float*)d_in[1];
    const float* Ww = (const float*)d_in[2];
    const float* Wb = (const float*)d_in[3];
    const float* Uw = (const float*)d_in[4];
    const float* Ub = (const float*)d_in[5];
    const float* Vw = (const float*)d_in[6];
    const float* Vb = (const float*)d_in[7];
    float* out = (float*)d_out;

    cudaFuncSetAttribute(k_main, cudaFuncAttributeMaxDynamicSharedMemorySize,
                         SMEM_TOTAL);

    k_prep<<<577, 256>>>(Uw, s, Ww, Wb, Ub);
    k_main<<<NCTAS, 128, SMEM_TOTAL>>>(h, Vw, Vb, out);
}